// round 15
// baseline (speedup 1.0000x reference)
#include <cuda_runtime.h>
#include <cuda_fp16.h>
#include <math.h>
#include <stdint.h>

#define BATCH 32
#define NSEQ  512
#define EMB   128
#define NHEAD 8
#define HDIM  16
#define NROWS (BATCH*NSEQ)

// ---------------- scratch (u32 = half2; [row][64 pairs]) ----------------
#define PR 64
// A-side operands: split (hi + lo)
__device__ __align__(16) uint32_t gNh[NROWS*PR],  gNl[NROWS*PR];
__device__ __align__(16) uint32_t gGh[NROWS*PR],  gGl[NROWS*PR];
__device__ __align__(16) uint32_t gO1h[NROWS*PR], gO1l[NROWS*PR];
__device__ __align__(16) uint32_t gO2h[NROWS*PR], gO2l[NROWS*PR];
__device__ __align__(16) uint32_t gMHh[NROWS*PR], gMHl[NROWS*PR];
// B-side operands: hi only
__device__ __align__(16) uint32_t gSHKh[NROWS*PR];
__device__ __align__(16) uint32_t gKh[NROWS*PR],  gVh[NROWS*PR];
__device__ __align__(16) uint32_t gKeh[NROWS*PR], gVeh[NROWS*PR];
__device__ __align__(16) uint32_t gWh[10*8192];
// fp32 K-split partials for qproj
__device__ __align__(16) float gQpart[4*NROWS*EMB];

__device__ __forceinline__ float fast_tanh(float x) {
    float e = __expf(2.f * x);
    return 1.f - __fdividef(2.f, e + 1.f);
}

__device__ __forceinline__ uint32_t cvt2h(float x, float y) {
    __half2 hv = __floats2half2_rn(x, y);
    return *reinterpret_cast<uint32_t*>(&hv);
}
__device__ __forceinline__ void split2h(float x, float y, uint32_t& h, uint32_t& l) {
    __half2 hv = __floats2half2_rn(x, y);
    h = *reinterpret_cast<uint32_t*>(&hv);
    float2 hf = __half22float2(hv);
    __half2 lv = __floats2half2_rn(x - hf.x, y - hf.y);
    l = *reinterpret_cast<uint32_t*>(&lv);
}

__device__ __forceinline__ void mma_f16(float* d,
        uint32_t a0, uint32_t a1, uint32_t a2, uint32_t a3,
        uint32_t b0, uint32_t b1) {
    asm volatile(
        "mma.sync.aligned.m16n8k16.row.col.f32.f16.f16.f32 "
        "{%0,%1,%2,%3}, {%4,%5,%6,%7}, {%8,%9}, {%0,%1,%2,%3};"
        : "+f"(d[0]), "+f"(d[1]), "+f"(d[2]), "+f"(d[3])
        : "r"(a0), "r"(a1), "r"(a2), "r"(a3), "r"(b0), "r"(b1));
}

__device__ __forceinline__ uint32_t smem_u32(const void* p) {
    uint32_t a;
    asm("{ .reg .u64 t; cvta.to.shared.u64 t, %1; cvt.u32.u64 %0, t; }"
        : "=r"(a) : "l"(p));
    return a;
}
#define LDSM_X2(r0, r1, addr) \
    asm volatile("ldmatrix.sync.aligned.m8n8.x2.shared.b16 {%0,%1}, [%2];" \
                 : "=r"(r0), "=r"(r1) : "r"(addr))
#define LDSM_X2_T(r0, r1, addr) \
    asm volatile("ldmatrix.sync.aligned.m8n8.x2.trans.shared.b16 {%0,%1}, [%2];" \
                 : "=r"(r0), "=r"(r1) : "r"(addr))

// ======================================================================
// prep kernels
// ======================================================================
__global__ void __launch_bounds__(256) prep_w(
        const float* __restrict__ W0, const float* __restrict__ W1,
        const float* __restrict__ W2, const float* __restrict__ W3,
        const float* __restrict__ W4, const float* __restrict__ W5,
        const float* __restrict__ W6, const float* __restrict__ W7,
        const float* __restrict__ W8, const float* __restrict__ W9) {
    const float* Ws[10] = {W0, W1, W2, W3, W4, W5, W6, W7, W8, W9};
    int w = blockIdx.y;
    int i = blockIdx.x * 256 + threadIdx.x;   // 0..8191
    int n = i >> 6, kp = i & 63;
    const float* W = Ws[w];
    gWh[w * 8192 + i] = cvt2h(W[(2 * kp) * 128 + n], W[(2 * kp + 1) * 128 + n]);
}

__global__ void __launch_bounds__(256) prep_in(
        const float* __restrict__ nodes, const float* __restrict__ graph) {
    int i = blockIdx.x * 256 + threadIdx.x;
    int row = i >> 6, kp = i & 63;
    float2 n2 = *reinterpret_cast<const float2*>(&nodes[(size_t)row * 128 + 2 * kp]);
    float2 g2 = *reinterpret_cast<const float2*>(&graph[(size_t)row * 128 + 2 * kp]);
    uint32_t h, l;
    split2h(n2.x, n2.y, h, l);  gNh[i] = h;  gNl[i] = l;
    split2h(g2.x, g2.y, h, l);  gGh[i] = h;  gGl[i] = l;
    gSHKh[i] = cvt2h(n2.x + g2.x, n2.y + g2.y);
}

// ======================================================================
// GEMM machinery: M-tile 64, N 128, BK 16 (8 pairs), double-buffered.
// A split (h+l), B hi-only. 2 MMAs per (nt, k-step).
// ======================================================================
#define SStr 12

struct U2x2 { uint2 h, l; };

__device__ __forceinline__ U2x2 ldAcp(const uint32_t* __restrict__ srcH,
                                      const uint32_t* __restrict__ srcL,
                                      int row0, int kp0, int t) {
    int r = t >> 2, pp = (t & 3) * 2;
    size_t off = (size_t)(row0 + r) * PR + kp0 + pp;
    U2x2 v;
    v.h = *reinterpret_cast<const uint2*>(srcH + off);
    v.l = *reinterpret_cast<const uint2*>(srcL + off);
    return v;
}
__device__ __forceinline__ void stAcp(U2x2 v, int t, uint32_t* sAh, uint32_t* sAl) {
    int r = t >> 2, pp = (t & 3) * 2;
    sAh[r * SStr + pp] = v.h.x; sAh[r * SStr + pp + 1] = v.h.y;
    sAl[r * SStr + pp] = v.l.x; sAl[r * SStr + pp + 1] = v.l.y;
}

__device__ __forceinline__ uint4 ldBcp(const uint32_t* __restrict__ srcH,
                                       int kp0, int t) {
    int n = t >> 1, kq = (t & 1) * 4;
    return *reinterpret_cast<const uint4*>(srcH + (size_t)n * PR + kp0 + kq);
}
__device__ __forceinline__ void stBcp(uint4 v, int t, uint32_t* sBh) {
    int n = t >> 1, kq = (t & 1) * 4;
    sBh[n * SStr + kq]     = v.x; sBh[n * SStr + kq + 1] = v.y;
    sBh[n * SStr + kq + 2] = v.z; sBh[n * SStr + kq + 3] = v.w;
}

__device__ __forceinline__ float4 ldA64(const float* __restrict__ X, int row0, int k0, int t) {
    int r = t >> 2, k4 = (t & 3) * 4;
    return *reinterpret_cast<const float4*>(&X[(size_t)(row0 + r) * 128 + k0 + k4]);
}
__device__ __forceinline__ void stA64(float4 v, int t, uint32_t* sh, uint32_t* sl) {
    int r = t >> 2, k4 = (t & 3) * 4;
    uint32_t h0, l0, h1, l1;
    split2h(v.x, v.y, h0, l0);
    split2h(v.z, v.w, h1, l1);
    int base = r * SStr + (k4 >> 1);
    sh[base] = h0; sh[base + 1] = h1;
    sl[base] = l0; sl[base + 1] = l1;
}

__device__ __forceinline__ void mma64(const uint32_t* __restrict__ sAh,
                                      const uint32_t* __restrict__ sAl,
                                      const uint32_t* __restrict__ sBh,
                                      int mg, int nh, int g, int tq, float acc[8][4]) {
    int m0 = mg * 16;
    uint32_t ah0 = sAh[(m0 + g) * SStr + tq],     ah1 = sAh[(m0 + 8 + g) * SStr + tq];
    uint32_t ah2 = sAh[(m0 + g) * SStr + tq + 4], ah3 = sAh[(m0 + 8 + g) * SStr + tq + 4];
    uint32_t al0 = sAl[(m0 + g) * SStr + tq],     al1 = sAl[(m0 + 8 + g) * SStr + tq];
    uint32_t al2 = sAl[(m0 + g) * SStr + tq + 4], al3 = sAl[(m0 + 8 + g) * SStr + tq + 4];
#pragma unroll
    for (int nt = 0; nt < 8; nt++) {
        int n = nh * 64 + nt * 8 + g;
        uint32_t bh0 = sBh[n * SStr + tq], bh1 = sBh[n * SStr + tq + 4];
        mma_f16(acc[nt], ah0, ah1, ah2, ah3, bh0, bh1);
        mma_f16(acc[nt], al0, al1, al2, al3, bh0, bh1);
    }
}

// epilogue writing hi-only (for K/V)
__device__ __forceinline__ void epi_h(float acc[8][4], int row0, int mg, int nh,
                                      int g, int tq, uint32_t* __restrict__ dh) {
    size_t r_lo = (size_t)row0 + mg * 16 + g;
    size_t r_hi = r_lo + 8;
#pragma unroll
    for (int nt = 0; nt < 8; nt++) {
        int pair = nh * 32 + nt * 4 + tq;
        dh[r_lo * PR + pair] = cvt2h(acc[nt][0], acc[nt][1]);
        dh[r_hi * PR + pair] = cvt2h(acc[nt][2], acc[nt][3]);
    }
}
// epilogue writing split (for O/MH)
__device__ __forceinline__ void epi_split(float acc[8][4], int row0, int mg, int nh,
                                          int g, int tq,
                                          uint32_t* __restrict__ dh, uint32_t* __restrict__ dl) {
    size_t r_lo = (size_t)row0 + mg * 16 + g;
    size_t r_hi = r_lo + 8;
#pragma unroll
    for (int nt = 0; nt < 8; nt++) {
        int pair = nh * 32 + nt * 4 + tq;
        uint32_t h, l;
        split2h(acc[nt][0], acc[nt][1], h, l);
        dh[r_lo * PR + pair] = h; dl[r_lo * PR + pair] = l;
        split2h(acc[nt][2], acc[nt][3], h, l);
        dh[r_hi * PR + pair] = h; dl[r_hi * PR + pair] = l;
    }
}

__device__ __forceinline__ void epi_f32(float acc[8][4], int row0, int mg, int nh,
                                        int g, int tq, float* __restrict__ dst) {
    size_t r_lo = (size_t)row0 + mg * 16 + g;
    size_t r_hi = r_lo + 8;
#pragma unroll
    for (int nt = 0; nt < 8; nt++) {
        int c = nh * 64 + nt * 8 + tq * 2;
        *reinterpret_cast<float2*>(dst + r_lo * EMB + c) = make_float2(acc[nt][0], acc[nt][1]);
        *reinterpret_cast<float2*>(dst + r_hi * EMB + c) = make_float2(acc[nt][2], acc[nt][3]);
    }
}

// ======================================================================
// gemm_all: grid (256, 8), block 256.
// ======================================================================
__global__ void __launch_bounds__(256) gemm_all(
        const float* __restrict__ X0, const float* __restrict__ X1,
        const float* __restrict__ X2, const float* __restrict__ X3) {
    __shared__ uint32_t sAh[2][64 * SStr], sAl[2][64 * SStr];
    __shared__ uint32_t sBh[2][128 * SStr];
    int z = blockIdx.y;
    int t = threadIdx.x;
    int lane = t & 31, wid = t >> 5;
    int g = lane >> 2, tq = lane & 3;
    int mg = wid >> 1, nh = wid & 1;
    int row0 = blockIdx.x * 64;

    const uint32_t* Bh = gWh + (size_t)z * 8192;

    float acc[8][4];
#pragma unroll
    for (int nt = 0; nt < 8; nt++)
#pragma unroll
        for (int j = 0; j < 4; j++) acc[nt][j] = 0.f;

    if (z < 4) {
        const uint32_t* Ah = (z < 2) ? gNh : gGh;
        const uint32_t* Al = (z < 2) ? gNl : gGl;
        U2x2 pa = ldAcp(Ah, Al, row0, 0, t);
        uint4 pb = ldBcp(Bh, 0, t);
        int buf = 0;
        for (int s = 0; s < 8; s++) {
            stAcp(pa, t, sAh[buf], sAl[buf]);
            stBcp(pb, t, sBh[buf]);
            __syncthreads();
            if (s < 7) {
                pa = ldAcp(Ah, Al, row0, (s + 1) * 8, t);
                pb = ldBcp(Bh, (s + 1) * 8, t);
            }
            mma64(sAh[buf], sAl[buf], sBh[buf], mg, nh, g, tq, acc);
            buf ^= 1;
        }
        uint32_t* Oh = (z == 0) ? gKh : (z == 1) ? gVh : (z == 2) ? gKeh : gVeh;
        epi_h(acc, row0, mg, nh, g, tq, Oh);
    } else {
        const float* Xs[4] = {X0, X1, X2, X3};
        const float* X = Xs[z - 4];
        float4 pa = ldA64(X, row0, 0, t);
        uint4 pb = ldBcp(Bh, 0, t);
        int buf = 0;
        for (int s = 0; s < 8; s++) {
            stA64(pa, t, sAh[buf], sAl[buf]);
            stBcp(pb, t, sBh[buf]);
            __syncthreads();
            if (s < 7) {
                pa = ldA64(X, row0, (s + 1) * 16, t);
                pb = ldBcp(Bh, (s + 1) * 8, t);
            }
            mma64(sAh[buf], sAl[buf], sBh[buf], mg, nh, g, tq, acc);
            buf ^= 1;
        }
        epi_f32(acc, row0, mg, nh, g, tq, gQpart + (size_t)(z - 4) * NROWS * EMB);
    }
}

// ======================================================================
// comb_k: MH = O1@W8 + O2@W9 + biases. grid (256), block 256. 16 steps.
// ======================================================================
__global__ void __launch_bounds__(256) comb_k(
        const float* __restrict__ b1, const float* __restrict__ b2) {
    __shared__ uint32_t sAh[2][64 * SStr], sAl[2][64 * SStr];
    __shared__ uint32_t sBh[2][128 * SStr];
    int t = threadIdx.x;
    int lane = t & 31, wid = t >> 5;
    int g = lane >> 2, tq = lane & 3;
    int mg = wid >> 1, nh = wid & 1;
    int row0 = blockIdx.x * 64;

    float acc[8][4];
#pragma unroll
    for (int nt = 0; nt < 8; nt++)
#pragma unroll
        for (int j = 0; j < 4; j++) acc[nt][j] = 0.f;

    U2x2 pa = ldAcp(gO1h, gO1l, row0, 0, t);
    uint4 pb = ldBcp(gWh + 8 * 8192, 0, t);
    int buf = 0;
    for (int s = 0; s < 16; s++) {
        stAcp(pa, t, sAh[buf], sAl[buf]);
        stBcp(pb, t, sBh[buf]);
        __syncthreads();
        if (s < 15) {
            int p = (s + 1) >> 3, kp0 = ((s + 1) & 7) * 8;
            const uint32_t* ah = p ? gO2h : gO1h;
            const uint32_t* al = p ? gO2l : gO1l;
            pa = ldAcp(ah, al, row0, kp0, t);
            pb = ldBcp(gWh + (size_t)(8 + p) * 8192, kp0, t);
        }
        mma64(sAh[buf], sAl[buf], sBh[buf], mg, nh, g, tq, acc);
        buf ^= 1;
    }

#pragma unroll
    for (int nt = 0; nt < 8; nt++) {
        int c = nh * 64 + nt * 8 + tq * 2;
        float2 bb1 = *reinterpret_cast<const float2*>(&b1[c]);
        float2 bb2 = *reinterpret_cast<const float2*>(&b2[c]);
        acc[nt][0] += bb1.x + bb2.x; acc[nt][1] += bb1.y + bb2.y;
        acc[nt][2] += bb1.x + bb2.x; acc[nt][3] += bb1.y + bb2.y;
    }
    epi_split(acc, row0, mg, nh, g, tq, gMHh, gMHl);
}

// ======================================================================
// score: logits = 10*tanh((MH @ shk^T)/sqrt(128)) + mask
// grid (4, 8, BATCH), block 256.
// ======================================================================
__global__ void __launch_bounds__(256) score_k(
        const float* __restrict__ mask, float* __restrict__ out) {
    __shared__ uint32_t sAh[2][64 * SStr], sAl[2][64 * SStr];
    __shared__ uint32_t sBh[2][128 * SStr];
    int t = threadIdx.x;
    int lane = t & 31, wid = t >> 5;
    int g = lane >> 2, tq = lane & 3;
    int mg = wid >> 1, nh = wid & 1;
    int b = blockIdx.z;
    int c0 = blockIdx.x * 128, r0 = blockIdx.y * 64;
    int arow0 = b * NSEQ + r0;
    const uint32_t* Bh = gSHKh + (size_t)(b * NSEQ + c0) * PR;

    float acc[8][4];
#pragma unroll
    for (int nt = 0; nt < 8; nt++)
#pragma unroll
        for (int j = 0; j < 4; j++) acc[nt][j] = 0.f;

    U2x2 pa = ldAcp(gMHh, gMHl, arow0, 0, t);
    uint4 pb = ldBcp(Bh, 0, t);
    int buf = 0;
    for (int s = 0; s < 8; s++) {
        stAcp(pa, t, sAh[buf], sAl[buf]);
        stBcp(pb, t, sBh[buf]);
        __syncthreads();
        if (s < 7) {
            pa = ldAcp(gMHh, gMHl, arow0, (s + 1) * 8, t);
            pb = ldBcp(Bh, (s + 1) * 8, t);
        }
        mma64(sAh[buf], sAl[buf], sBh[buf], mg, nh, g, tq, acc);
        buf ^= 1;
    }

    const float inv_sqrt_emb = 0.08838834764831845f;  // 1/sqrt(128)
    int r_lo = r0 + mg * 16 + g;
    int r_hi = r_lo + 8;
#pragma unroll
    for (int nt = 0; nt < 8; nt++) {
        int c = c0 + nh * 64 + nt * 8 + tq * 2;
        size_t gi0 = (size_t)(b * NSEQ + r_lo) * NSEQ + c;
        size_t gi1 = (size_t)(b * NSEQ + r_hi) * NSEQ + c;
        float2 m0 = *reinterpret_cast<const float2*>(&mask[gi0]);
        float2 m1 = *reinterpret_cast<const float2*>(&mask[gi1]);
        *reinterpret_cast<float2*>(&out[gi0]) = make_float2(
            fmaf(10.f, fast_tanh(acc[nt][0] * inv_sqrt_emb), m0.x),
            fmaf(10.f, fast_tanh(acc[nt][1] * inv_sqrt_emb), m0.y));
        *reinterpret_cast<float2*>(&out[gi1]) = make_float2(
            fmaf(10.f, fast_tanh(acc[nt][2] * inv_sqrt_emb), m1.x),
            fmaf(10.f, fast_tanh(acc[nt][3] * inv_sqrt_emb), m1.y));
    }
}

// ======================================================================
// dual attention: fp16 2-term (r13 math), hoisted smem addresses,
// double-buffered + prefetch, one sync/chunk. grid (NHEAD, 4, BATCH).
// ======================================================================
#define KStr 12   // u32 stride per key row (48B)
struct KVr { uint2 kh, vh; };

__global__ void __launch_bounds__(256) attn_kernel(const float* __restrict__ mask) {
    // [buf][attn]: 0 = attn1, 1 = attn2
    __shared__ __align__(16) uint32_t sK[2][2][32 * KStr];
    __shared__ __align__(16) uint32_t sV[2][2][32 * KStr];

    int t = threadIdx.x;
    int lane = t & 31, wid = t >> 5;
    int g = lane >> 2, tq = lane & 3;
    int b = blockIdx.z, h = blockIdx.x;
    int r0 = blockIdx.y * 128;
    int rw = wid * 16;

    // ---- Q fragments: sum 4 fp32 partials, then split ----
    uint32_t qh[4], ql[4];
    {
        size_t row_a = (size_t)(b * NSEQ + r0 + rw + g);
        size_t row_b = row_a + 8;
        int col0 = h * HDIM + 2 * tq;
#pragma unroll
        for (int pos = 0; pos < 4; pos++) {
            size_t row = (pos & 1) ? row_b : row_a;
            int col = col0 + ((pos >> 1) ? 8 : 0);
            float sx = 0.f, sy = 0.f;
#pragma unroll
            for (int p = 0; p < 4; p++) {
                float2 v = *reinterpret_cast<const float2*>(
                    gQpart + (size_t)p * NROWS * EMB + row * EMB + col);
                sx += v.x; sy += v.y;
            }
            split2h(sx, sy, qh[pos], ql[pos]);
        }
    }

    float o1[2][4] = {{0,0,0,0},{0,0,0,0}};
    float o2[2][4] = {{0,0,0,0},{0,0,0,0}};
    float la1 = 0.f, lb1 = 0.f, la2 = 0.f, lb2 = 0.f;

    int sidx = t & 127;
    int sm = sidx >> 2, pp = (sidx & 3) * 2;   // key row, u32 pair index {0,2,4,6}
    bool first_half = (t < 128);
    const uint32_t* srcKh = first_half ? gKh : gKeh;
    const uint32_t* srcVh = first_half ? gVh : gVeh;
    int cbase = first_half ? 0 : 1;

    const float* maskrow0 = mask + ((size_t)(b * NSEQ + r0 + rw + g) * NSEQ);
    const float* maskrow1 = maskrow0 + 8 * NSEQ;

    // per-lane ldmatrix offsets (bytes), hoisted for both buffers
    int l15 = lane & 15;
    int offK = (l15 & 7) * 48 + ((l15 >> 3) << 4);
    int offV = l15 * 48;
    uint32_t aK1b[2], aK2b[2], aV1b[2], aV2b[2];
#pragma unroll
    for (int bb = 0; bb < 2; bb++) {
        aK1b[bb] = smem_u32(&sK[bb][0][0]) + offK;
        aK2b[bb] = smem_u32(&sK[bb][1][0]) + offK;
        aV1b[bb] = smem_u32(&sV[bb][0][0]) + offV;
        aV2b[bb] = smem_u32(&sV[bb][1][0]) + offV;
    }
    int stidx = sm * KStr + pp;
    uint32_t stK[2], stV[2];
#pragma unroll
    for (int bb = 0; bb < 2; bb++) {
        stK[bb] = smem_u32(&sK[bb][cbase][stidx]);
        stV[bb] = smem_u32(&sV[bb][cbase][stidx]);
    }

    // prefetch chunk 0
    KVr pf;
    {
        size_t off = (size_t)(b * NSEQ + sm) * PR + h * 8 + pp;
        pf.kh = *reinterpret_cast<const uint2*>(srcKh + off);
        pf.vh = *reinterpret_cast<const uint2*>(srcVh + off);
    }

    int buf = 0;
    for (int ch = 0; ch < 16; ch++) {
        asm volatile("st.shared.v2.b32 [%0], {%1,%2};" :: "r"(stK[buf]), "r"(pf.kh.x), "r"(pf.kh.y) : "memory");
        asm volatile("st.shared.v2.b32 [%0], {%1,%2};" :: "r"(stV[buf]), "r"(pf.vh.x), "r"(pf.vh.y) : "memory");
        __syncthreads();
        if (ch < 15) {
            size_t off = (size_t)(b * NSEQ + (ch + 1) * 32 + sm) * PR + h * 8 + pp;
            pf.kh = *reinterpret_cast<const uint2*>(srcKh + off);
            pf.vh = *reinterpret_cast<const uint2*>(srcVh + off);
        }
        int c0 = ch * 32;

        float S1[4][4], S2[4][4];
#pragma unroll
        for (int nt = 0; nt < 4; nt++) {
#pragma unroll
            for (int j = 0; j < 4; j++) { S1[nt][j] = 0.f; S2[nt][j] = 0.f; }
            uint32_t b0, b1;
            LDSM_X2(b0, b1, aK1b[buf] + nt * 384);
            mma_f16(S1[nt], qh[0], qh[1], qh[2], qh[3], b0, b1);
            mma_f16(S1[nt], ql[0], ql[1], ql[2], ql[3], b0, b1);
            uint32_t e0, e1;
            LDSM_X2(e0, e1, aK2b[buf] + nt * 384);
            mma_f16(S2[nt], qh[0], qh[1], qh[2], qh[3], e0, e1);
            mma_f16(S2[nt], ql[0], ql[1], ql[2], ql[3], e0, e1);
        }

#pragma unroll
        for (int nt = 0; nt < 4; nt++) {
            int cc = c0 + nt * 8 + tq * 2;
            float2 m0 = *reinterpret_cast<const float2*>(maskrow0 + cc);
            float2 m1 = *reinterpret_cast<const float2*>(maskrow1 + cc);
            float p;
            p = __expf(fminf(fmaf(S1[nt][0], 0.25f, m0.x), 10.f)); S1[nt][0] = p; la1 += p;
            p = __expf(fminf(fmaf(S1[nt][1], 0.25f, m0.y), 10.f)); S1[nt][1] = p; la1 += p;
            p = __expf(fminf(fmaf(S1[nt][2], 0.25f, m1.x), 10.f)); S1[nt][2] = p; lb1 += p;
            p = __expf(fminf(fmaf(S1[nt][3], 0.25f, m1.y), 10.f)); S1[nt][3] = p; lb1 += p;
            p = __expf(fminf(fmaf(S2[nt][0], 0.25f, m0.x), 10.f)); S2[nt][0] = p; la2 += p;
            p = __expf(fminf(fmaf(S2[nt][1], 0.25f, m0.y), 10.f)); S2[nt][1] = p; la2 += p;
            p = __expf(fminf(fmaf(S2[nt][2], 0.25f, m1.x), 10.f)); S2[nt][2] = p; lb2 += p;
            p = __expf(fminf(fmaf(S2[nt][3], 0.25f, m1.y), 10.f)); S2[nt][3] = p; lb2 += p;
        }

#pragma unroll
        for (int ks = 0; ks < 2; ks++) {
            uint32_t a1h[4], a1l[4], a2h[4], a2l[4];
            split2h(S1[2*ks][0],   S1[2*ks][1],   a1h[0], a1l[0]);
            split2h(S1[2*ks][2],   S1[2*ks][3],   a1h[1], a1l[1]);
            split2h(S1[2*ks+1][0], S1[2*ks+1][1], a1h[2], a1l[2]);
            split2h(S1[2*ks+1][2], S1[2*ks+1][3], a1h[3], a1l[3]);
            split2h(S2[2*ks][0],   S2[2*ks][1],   a2h[0], a2l[0]);
            split2h(S2[2*ks][2],   S2[2*ks][3],   a2h[1], a2l[1]);
            split2h(S2[2*ks+1][0], S2[2*ks+1][1], a2h[2], a2l[2]);
            split2h(S2[2*ks+1][2], S2[2*ks+1][3], a2h[3], a2l[3]);
            uint32_t kof = (uint32_t)(ks * 16) * 48;
#pragma unroll
            for (int dt = 0; dt < 2; dt++) {
                uint32_t dof = kof + dt * 16;
                uint32_t v0, v1;
                LDSM_X2_T(v0, v1, aV1b[buf] + dof);
                mma_f16(o1[dt], a1h[0], a1h[1], a1h[2], a1h[3], v0, v1);
                mma_f16(o1[dt], a1l[0], a1l[1], a1l[2], a1l[3], v0, v1);
                uint32_t w0, w1;
                LDSM_X2_T(w0, w1, aV2b[buf] + dof);
                mma_f16(o2[dt], a2h[0], a2h[1], a2h[2], a2h[3], w0, w1);
                mma_f16(o2[dt], a2l[0], a2l[1], a2l[2], a2l[3], w0, w1);
            }
        }
        buf ^= 1;
    }

    la1 += __shfl_xor_sync(0xffffffffu, la1, 1); la1 += __shfl_xor_sync(0xffffffffu, la1, 2);
    lb1 += __shfl_xor_sync(0xffffffffu, lb1, 1); lb1 += __shfl_xor_sync(0xffffffffu, lb1, 2);
    la2 += __shfl_xor_sync(0xffffffffu, la2, 1); la2 += __shfl_xor_sync(0xffffffffu, la2, 2);
    lb2 += __shfl_xor_sync(0xffffffffu, lb2, 1); lb2 += __shfl_xor_sync(0xffffffffu, lb2, 2);
    float ia1 = 1.f / la1, ib1 = 1.f / lb1, ia2 = 1.f / la2, ib2 = 1.f / lb2;

    {
        size_t ra = (size_t)(b * NSEQ + r0 + rw + g) * PR + h * 8;
        size_t rb = ra + 8 * PR;
#pragma unroll
        for (int dt = 0; dt < 2; dt++) {
            int pair = dt * 4 + tq;
            uint32_t hh, ll;
            split2h(o1[dt][0] * ia1, o1[dt][1] * ia1, hh, ll);
            gO1h[ra + pair] = hh; gO1l[ra + pair] = ll;
            split2h(o1[dt][2] * ib1, o1[dt][3] * ib1, hh, ll);
            gO1h[rb + pair] = hh; gO1l[rb + pair] = ll;
            split2h(o2[dt][0] * ia2, o2[dt][1] * ia2, hh, ll);
            gO2h[ra + pair] = hh; gO2l[ra + pair] = ll;
            split2h(o2[dt][2] * ib2, o2[dt][3] * ib2, hh, ll);
            gO2h[rb + pair] = hh; gO2l[rb + pair] = ll;
        }
    }
}

// ---------------- in-place row softmax (no max pass: logits bounded) ----
__global__ void softmax_kernel(float* __restrict__ out) {
    float4* p = reinterpret_cast<float4*>(out + (size_t)blockIdx.x * NSEQ);
    int t = threadIdx.x;  // 128 threads
    float4 v = p[t];
    v.x = __expf(v.x); v.y = __expf(v.y);
    v.z = __expf(v.z); v.w = __expf(v.w);
    float sum = v.x + v.y + v.z + v.w;
#pragma unroll
    for (int o = 16; o; o >>= 1) sum += __shfl_xor_sync(0xffffffffu, sum, o);
    __shared__ float ss[4];
    if ((t & 31) == 0) ss[t >> 5] = sum;
    __syncthreads();
    sum = ss[0] + ss[1] + ss[2] + ss[3];

    float inv = 1.f / sum;
    v.x *= inv; v.y *= inv; v.z *= inv; v.w *= inv;
    p[t] = v;
}

// ---------------- launch ----------------
extern "C" void kernel_launch(void* const* d_in, const int* in_sizes, int n_in,
                              void* d_out, int out_size) {
    const float* enc_nodes = (const float*)d_in[0];
    const float* enc_graph = (const float*)d_in[1];
    const float* enc_q1    = (const float*)d_in[2];
    const float* enc_fg    = (const float*)d_in[3];
    const float* enc_ln    = (const float*)d_in[4];
    const float* enc_lg    = (const float*)d_in[5];
    const float* mask      = (const float*)d_in[6];
    const float* Wq_first  = (const float*)d_in[7];
    const float* Wq_last   = (const float*)d_in[8];
    const float* Wk        = (const float*)d_in[9];
    const float* Wv        = (const float*)d_in[10];
    const float* Wq_first_e= (const float*)d_in[11];
    const float* Wq_last_e = (const float*)d_in[12];
    const float* Wk_e      = (const float*)d_in[13];
    const float* Wv_e      = (const float*)d_in[14];
    const float* Wcomb1    = (const float*)d_in[15];
    const float* bcomb1    = (const float*)d_in[16];
    const float* Wcomb2    = (const float*)d_in[17];
    const float* bcomb2    = (const float*)d_in[18];
    float* out = (float*)d_out;

    prep_w<<<dim3(32, 10), 256>>>(Wk, Wv, Wk_e, Wv_e,
                                  Wq_first, Wq_last, Wq_first_e, Wq_last_e,
                                  Wcomb1, Wcomb2);
    prep_in<<<(NROWS * PR) / 256, 256>>>(enc_nodes, enc_graph);
    gemm_all<<<dim3(256, 8), 256>>>(enc_q1, enc_ln, enc_fg, enc_lg);
    attn_kernel<<<dim3(NHEAD, 4, BATCH), 256>>>(mask);
    comb_k<<<256, 256>>>(bcomb1, bcomb2);
    score_k<<<dim3(4, 8, BATCH), 256>>>(mask, out);
    softmax_kernel<<<BATCH * NSEQ, 128>>>(out);
}

// round 16
// speedup vs baseline: 1.0376x; 1.0376x over previous
#include <cuda_runtime.h>
#include <cuda_fp16.h>
#include <math.h>
#include <stdint.h>

#define BATCH 32
#define NSEQ  512
#define EMB   128
#define NHEAD 8
#define HDIM  16
#define NROWS (BATCH*NSEQ)

// ---------------- scratch (u32 = half2; [row][64 pairs]) ----------------
#define PR 64
// A-side operands: split (hi + lo)
__device__ __align__(16) uint32_t gNh[NROWS*PR],  gNl[NROWS*PR];
__device__ __align__(16) uint32_t gGh[NROWS*PR],  gGl[NROWS*PR];
__device__ __align__(16) uint32_t gO1h[NROWS*PR], gO1l[NROWS*PR];
__device__ __align__(16) uint32_t gO2h[NROWS*PR], gO2l[NROWS*PR];
__device__ __align__(16) uint32_t gMHh[NROWS*PR], gMHl[NROWS*PR];
// B-side operands: hi only
__device__ __align__(16) uint32_t gSHKh[NROWS*PR];
__device__ __align__(16) uint32_t gKh[NROWS*PR],  gVh[NROWS*PR];
__device__ __align__(16) uint32_t gKeh[NROWS*PR], gVeh[NROWS*PR];
__device__ __align__(16) uint32_t gWh[10*8192];
// fp32 K-split partials for qproj
__device__ __align__(16) float gQpart[4*NROWS*EMB];

__device__ __forceinline__ float fast_tanh(float x) {
    float e = __expf(2.f * x);
    return 1.f - __fdividef(2.f, e + 1.f);
}

__device__ __forceinline__ uint32_t cvt2h(float x, float y) {
    __half2 hv = __floats2half2_rn(x, y);
    return *reinterpret_cast<uint32_t*>(&hv);
}
__device__ __forceinline__ void split2h(float x, float y, uint32_t& h, uint32_t& l) {
    __half2 hv = __floats2half2_rn(x, y);
    h = *reinterpret_cast<uint32_t*>(&hv);
    float2 hf = __half22float2(hv);
    __half2 lv = __floats2half2_rn(x - hf.x, y - hf.y);
    l = *reinterpret_cast<uint32_t*>(&lv);
}

__device__ __forceinline__ void mma_f16(float* d,
        uint32_t a0, uint32_t a1, uint32_t a2, uint32_t a3,
        uint32_t b0, uint32_t b1) {
    asm volatile(
        "mma.sync.aligned.m16n8k16.row.col.f32.f16.f16.f32 "
        "{%0,%1,%2,%3}, {%4,%5,%6,%7}, {%8,%9}, {%0,%1,%2,%3};"
        : "+f"(d[0]), "+f"(d[1]), "+f"(d[2]), "+f"(d[3])
        : "r"(a0), "r"(a1), "r"(a2), "r"(a3), "r"(b0), "r"(b1));
}

__device__ __forceinline__ uint32_t smem_u32(const void* p) {
    uint32_t a;
    asm("{ .reg .u64 t; cvta.to.shared.u64 t, %1; cvt.u32.u64 %0, t; }"
        : "=r"(a) : "l"(p));
    return a;
}
#define LDSM_X2(r0, r1, addr) \
    asm volatile("ldmatrix.sync.aligned.m8n8.x2.shared.b16 {%0,%1}, [%2];" \
                 : "=r"(r0), "=r"(r1) : "r"(addr))
#define LDSM_X2_T(r0, r1, addr) \
    asm volatile("ldmatrix.sync.aligned.m8n8.x2.trans.shared.b16 {%0,%1}, [%2];" \
                 : "=r"(r0), "=r"(r1) : "r"(addr))

// ======================================================================
// prep kernels
// ======================================================================
__global__ void __launch_bounds__(256) prep_w(
        const float* __restrict__ W0, const float* __restrict__ W1,
        const float* __restrict__ W2, const float* __restrict__ W3,
        const float* __restrict__ W4, const float* __restrict__ W5,
        const float* __restrict__ W6, const float* __restrict__ W7,
        const float* __restrict__ W8, const float* __restrict__ W9) {
    const float* Ws[10] = {W0, W1, W2, W3, W4, W5, W6, W7, W8, W9};
    int w = blockIdx.y;
    int i = blockIdx.x * 256 + threadIdx.x;   // 0..8191
    int n = i >> 6, kp = i & 63;
    const float* W = Ws[w];
    gWh[w * 8192 + i] = cvt2h(W[(2 * kp) * 128 + n], W[(2 * kp + 1) * 128 + n]);
}

__global__ void __launch_bounds__(256) prep_in(
        const float* __restrict__ nodes, const float* __restrict__ graph) {
    int i = blockIdx.x * 256 + threadIdx.x;
    int row = i >> 6, kp = i & 63;
    float2 n2 = *reinterpret_cast<const float2*>(&nodes[(size_t)row * 128 + 2 * kp]);
    float2 g2 = *reinterpret_cast<const float2*>(&graph[(size_t)row * 128 + 2 * kp]);
    uint32_t h, l;
    split2h(n2.x, n2.y, h, l);  gNh[i] = h;  gNl[i] = l;
    split2h(g2.x, g2.y, h, l);  gGh[i] = h;  gGl[i] = l;
    gSHKh[i] = cvt2h(n2.x + g2.x, n2.y + g2.y);
}

// ======================================================================
// GEMM machinery: M-tile 64, N 128, BK 16 (8 pairs), double-buffered.
// A split (h+l), B hi-only. 2 MMAs per (nt, k-step).
// ======================================================================
#define SStr 12

struct U2x2 { uint2 h, l; };

__device__ __forceinline__ U2x2 ldAcp(const uint32_t* __restrict__ srcH,
                                      const uint32_t* __restrict__ srcL,
                                      int row0, int kp0, int t) {
    int r = t >> 2, pp = (t & 3) * 2;
    size_t off = (size_t)(row0 + r) * PR + kp0 + pp;
    U2x2 v;
    v.h = *reinterpret_cast<const uint2*>(srcH + off);
    v.l = *reinterpret_cast<const uint2*>(srcL + off);
    return v;
}
__device__ __forceinline__ void stAcp(U2x2 v, int t, uint32_t* sAh, uint32_t* sAl) {
    int r = t >> 2, pp = (t & 3) * 2;
    sAh[r * SStr + pp] = v.h.x; sAh[r * SStr + pp + 1] = v.h.y;
    sAl[r * SStr + pp] = v.l.x; sAl[r * SStr + pp + 1] = v.l.y;
}

__device__ __forceinline__ uint4 ldBcp(const uint32_t* __restrict__ srcH,
                                       int kp0, int t) {
    int n = t >> 1, kq = (t & 1) * 4;
    return *reinterpret_cast<const uint4*>(srcH + (size_t)n * PR + kp0 + kq);
}
__device__ __forceinline__ void stBcp(uint4 v, int t, uint32_t* sBh) {
    int n = t >> 1, kq = (t & 1) * 4;
    sBh[n * SStr + kq]     = v.x; sBh[n * SStr + kq + 1] = v.y;
    sBh[n * SStr + kq + 2] = v.z; sBh[n * SStr + kq + 3] = v.w;
}

__device__ __forceinline__ float4 ldA64(const float* __restrict__ X, int row0, int k0, int t) {
    int r = t >> 2, k4 = (t & 3) * 4;
    return *reinterpret_cast<const float4*>(&X[(size_t)(row0 + r) * 128 + k0 + k4]);
}
__device__ __forceinline__ void stA64(float4 v, int t, uint32_t* sh, uint32_t* sl) {
    int r = t >> 2, k4 = (t & 3) * 4;
    uint32_t h0, l0, h1, l1;
    split2h(v.x, v.y, h0, l0);
    split2h(v.z, v.w, h1, l1);
    int base = r * SStr + (k4 >> 1);
    sh[base] = h0; sh[base + 1] = h1;
    sl[base] = l0; sl[base + 1] = l1;
}

__device__ __forceinline__ void mma64(const uint32_t* __restrict__ sAh,
                                      const uint32_t* __restrict__ sAl,
                                      const uint32_t* __restrict__ sBh,
                                      int mg, int nh, int g, int tq, float acc[8][4]) {
    int m0 = mg * 16;
    uint32_t ah0 = sAh[(m0 + g) * SStr + tq],     ah1 = sAh[(m0 + 8 + g) * SStr + tq];
    uint32_t ah2 = sAh[(m0 + g) * SStr + tq + 4], ah3 = sAh[(m0 + 8 + g) * SStr + tq + 4];
    uint32_t al0 = sAl[(m0 + g) * SStr + tq],     al1 = sAl[(m0 + 8 + g) * SStr + tq];
    uint32_t al2 = sAl[(m0 + g) * SStr + tq + 4], al3 = sAl[(m0 + 8 + g) * SStr + tq + 4];
#pragma unroll
    for (int nt = 0; nt < 8; nt++) {
        int n = nh * 64 + nt * 8 + g;
        uint32_t bh0 = sBh[n * SStr + tq], bh1 = sBh[n * SStr + tq + 4];
        mma_f16(acc[nt], ah0, ah1, ah2, ah3, bh0, bh1);
        mma_f16(acc[nt], al0, al1, al2, al3, bh0, bh1);
    }
}

// epilogue writing hi-only (for K/V)
__device__ __forceinline__ void epi_h(float acc[8][4], int row0, int mg, int nh,
                                      int g, int tq, uint32_t* __restrict__ dh) {
    size_t r_lo = (size_t)row0 + mg * 16 + g;
    size_t r_hi = r_lo + 8;
#pragma unroll
    for (int nt = 0; nt < 8; nt++) {
        int pair = nh * 32 + nt * 4 + tq;
        dh[r_lo * PR + pair] = cvt2h(acc[nt][0], acc[nt][1]);
        dh[r_hi * PR + pair] = cvt2h(acc[nt][2], acc[nt][3]);
    }
}
// epilogue writing split (for O/MH)
__device__ __forceinline__ void epi_split(float acc[8][4], int row0, int mg, int nh,
                                          int g, int tq,
                                          uint32_t* __restrict__ dh, uint32_t* __restrict__ dl) {
    size_t r_lo = (size_t)row0 + mg * 16 + g;
    size_t r_hi = r_lo + 8;
#pragma unroll
    for (int nt = 0; nt < 8; nt++) {
        int pair = nh * 32 + nt * 4 + tq;
        uint32_t h, l;
        split2h(acc[nt][0], acc[nt][1], h, l);
        dh[r_lo * PR + pair] = h; dl[r_lo * PR + pair] = l;
        split2h(acc[nt][2], acc[nt][3], h, l);
        dh[r_hi * PR + pair] = h; dl[r_hi * PR + pair] = l;
    }
}

__device__ __forceinline__ void epi_f32(float acc[8][4], int row0, int mg, int nh,
                                        int g, int tq, float* __restrict__ dst) {
    size_t r_lo = (size_t)row0 + mg * 16 + g;
    size_t r_hi = r_lo + 8;
#pragma unroll
    for (int nt = 0; nt < 8; nt++) {
        int c = nh * 64 + nt * 8 + tq * 2;
        *reinterpret_cast<float2*>(dst + r_lo * EMB + c) = make_float2(acc[nt][0], acc[nt][1]);
        *reinterpret_cast<float2*>(dst + r_hi * EMB + c) = make_float2(acc[nt][2], acc[nt][3]);
    }
}

// ======================================================================
// gemm_all: grid (256, 8), block 256.
// ======================================================================
__global__ void __launch_bounds__(256) gemm_all(
        const float* __restrict__ X0, const float* __restrict__ X1,
        const float* __restrict__ X2, const float* __restrict__ X3) {
    __shared__ uint32_t sAh[2][64 * SStr], sAl[2][64 * SStr];
    __shared__ uint32_t sBh[2][128 * SStr];
    int z = blockIdx.y;
    int t = threadIdx.x;
    int lane = t & 31, wid = t >> 5;
    int g = lane >> 2, tq = lane & 3;
    int mg = wid >> 1, nh = wid & 1;
    int row0 = blockIdx.x * 64;

    const uint32_t* Bh = gWh + (size_t)z * 8192;

    float acc[8][4];
#pragma unroll
    for (int nt = 0; nt < 8; nt++)
#pragma unroll
        for (int j = 0; j < 4; j++) acc[nt][j] = 0.f;

    if (z < 4) {
        const uint32_t* Ah = (z < 2) ? gNh : gGh;
        const uint32_t* Al = (z < 2) ? gNl : gGl;
        U2x2 pa = ldAcp(Ah, Al, row0, 0, t);
        uint4 pb = ldBcp(Bh, 0, t);
        int buf = 0;
        for (int s = 0; s < 8; s++) {
            stAcp(pa, t, sAh[buf], sAl[buf]);
            stBcp(pb, t, sBh[buf]);
            __syncthreads();
            if (s < 7) {
                pa = ldAcp(Ah, Al, row0, (s + 1) * 8, t);
                pb = ldBcp(Bh, (s + 1) * 8, t);
            }
            mma64(sAh[buf], sAl[buf], sBh[buf], mg, nh, g, tq, acc);
            buf ^= 1;
        }
        uint32_t* Oh = (z == 0) ? gKh : (z == 1) ? gVh : (z == 2) ? gKeh : gVeh;
        epi_h(acc, row0, mg, nh, g, tq, Oh);
    } else {
        const float* Xs[4] = {X0, X1, X2, X3};
        const float* X = Xs[z - 4];
        float4 pa = ldA64(X, row0, 0, t);
        uint4 pb = ldBcp(Bh, 0, t);
        int buf = 0;
        for (int s = 0; s < 8; s++) {
            stA64(pa, t, sAh[buf], sAl[buf]);
            stBcp(pb, t, sBh[buf]);
            __syncthreads();
            if (s < 7) {
                pa = ldA64(X, row0, (s + 1) * 16, t);
                pb = ldBcp(Bh, (s + 1) * 8, t);
            }
            mma64(sAh[buf], sAl[buf], sBh[buf], mg, nh, g, tq, acc);
            buf ^= 1;
        }
        epi_f32(acc, row0, mg, nh, g, tq, gQpart + (size_t)(z - 4) * NROWS * EMB);
    }
}

// ======================================================================
// comb_k: MH = O1@W8 + O2@W9 + biases. grid (256), block 256. 16 steps.
// ======================================================================
__global__ void __launch_bounds__(256) comb_k(
        const float* __restrict__ b1, const float* __restrict__ b2) {
    __shared__ uint32_t sAh[2][64 * SStr], sAl[2][64 * SStr];
    __shared__ uint32_t sBh[2][128 * SStr];
    int t = threadIdx.x;
    int lane = t & 31, wid = t >> 5;
    int g = lane >> 2, tq = lane & 3;
    int mg = wid >> 1, nh = wid & 1;
    int row0 = blockIdx.x * 64;

    float acc[8][4];
#pragma unroll
    for (int nt = 0; nt < 8; nt++)
#pragma unroll
        for (int j = 0; j < 4; j++) acc[nt][j] = 0.f;

    U2x2 pa = ldAcp(gO1h, gO1l, row0, 0, t);
    uint4 pb = ldBcp(gWh + 8 * 8192, 0, t);
    int buf = 0;
    for (int s = 0; s < 16; s++) {
        stAcp(pa, t, sAh[buf], sAl[buf]);
        stBcp(pb, t, sBh[buf]);
        __syncthreads();
        if (s < 15) {
            int p = (s + 1) >> 3, kp0 = ((s + 1) & 7) * 8;
            const uint32_t* ah = p ? gO2h : gO1h;
            const uint32_t* al = p ? gO2l : gO1l;
            pa = ldAcp(ah, al, row0, kp0, t);
            pb = ldBcp(gWh + (size_t)(8 + p) * 8192, kp0, t);
        }
        mma64(sAh[buf], sAl[buf], sBh[buf], mg, nh, g, tq, acc);
        buf ^= 1;
    }

#pragma unroll
    for (int nt = 0; nt < 8; nt++) {
        int c = nh * 64 + nt * 8 + tq * 2;
        float2 bb1 = *reinterpret_cast<const float2*>(&b1[c]);
        float2 bb2 = *reinterpret_cast<const float2*>(&b2[c]);
        acc[nt][0] += bb1.x + bb2.x; acc[nt][1] += bb1.y + bb2.y;
        acc[nt][2] += bb1.x + bb2.x; acc[nt][3] += bb1.y + bb2.y;
    }
    epi_split(acc, row0, mg, nh, g, tq, gMHh, gMHl);
}

// ======================================================================
// score: logits = 10*tanh((MH @ shk^T)/sqrt(128)) + mask
// grid (4, 8, BATCH), block 256.
// ======================================================================
__global__ void __launch_bounds__(256) score_k(
        const float* __restrict__ mask, float* __restrict__ out) {
    __shared__ uint32_t sAh[2][64 * SStr], sAl[2][64 * SStr];
    __shared__ uint32_t sBh[2][128 * SStr];
    int t = threadIdx.x;
    int lane = t & 31, wid = t >> 5;
    int g = lane >> 2, tq = lane & 3;
    int mg = wid >> 1, nh = wid & 1;
    int b = blockIdx.z;
    int c0 = blockIdx.x * 128, r0 = blockIdx.y * 64;
    int arow0 = b * NSEQ + r0;
    const uint32_t* Bh = gSHKh + (size_t)(b * NSEQ + c0) * PR;

    float acc[8][4];
#pragma unroll
    for (int nt = 0; nt < 8; nt++)
#pragma unroll
        for (int j = 0; j < 4; j++) acc[nt][j] = 0.f;

    U2x2 pa = ldAcp(gMHh, gMHl, arow0, 0, t);
    uint4 pb = ldBcp(Bh, 0, t);
    int buf = 0;
    for (int s = 0; s < 8; s++) {
        stAcp(pa, t, sAh[buf], sAl[buf]);
        stBcp(pb, t, sBh[buf]);
        __syncthreads();
        if (s < 7) {
            pa = ldAcp(gMHh, gMHl, arow0, (s + 1) * 8, t);
            pb = ldBcp(Bh, (s + 1) * 8, t);
        }
        mma64(sAh[buf], sAl[buf], sBh[buf], mg, nh, g, tq, acc);
        buf ^= 1;
    }

    const float inv_sqrt_emb = 0.08838834764831845f;  // 1/sqrt(128)
    int r_lo = r0 + mg * 16 + g;
    int r_hi = r_lo + 8;
#pragma unroll
    for (int nt = 0; nt < 8; nt++) {
        int c = c0 + nh * 64 + nt * 8 + tq * 2;
        size_t gi0 = (size_t)(b * NSEQ + r_lo) * NSEQ + c;
        size_t gi1 = (size_t)(b * NSEQ + r_hi) * NSEQ + c;
        float2 m0 = *reinterpret_cast<const float2*>(&mask[gi0]);
        float2 m1 = *reinterpret_cast<const float2*>(&mask[gi1]);
        *reinterpret_cast<float2*>(&out[gi0]) = make_float2(
            fmaf(10.f, fast_tanh(acc[nt][0] * inv_sqrt_emb), m0.x),
            fmaf(10.f, fast_tanh(acc[nt][1] * inv_sqrt_emb), m0.y));
        *reinterpret_cast<float2*>(&out[gi1]) = make_float2(
            fmaf(10.f, fast_tanh(acc[nt][2] * inv_sqrt_emb), m1.x),
            fmaf(10.f, fast_tanh(acc[nt][3] * inv_sqrt_emb), m1.y));
    }
}

// ======================================================================
// dual attention: fp16 2-term, exact round-13 structure (addresses
// recomputed per chunk). Double-buffered + prefetch, one sync/chunk.
// grid (NHEAD, 4, BATCH), block 256.
// ======================================================================
#define KStr 12   // u32 stride per key row (48B)
struct KVr { uint2 kh, vh; };

__global__ void __launch_bounds__(256) attn_kernel(const float* __restrict__ mask) {
    // [buf][attn]: 0 = attn1, 1 = attn2
    __shared__ __align__(16) uint32_t sK[2][2][32 * KStr];
    __shared__ __align__(16) uint32_t sV[2][2][32 * KStr];

    int t = threadIdx.x;
    int lane = t & 31, wid = t >> 5;
    int g = lane >> 2, tq = lane & 3;
    int b = blockIdx.z, h = blockIdx.x;
    int r0 = blockIdx.y * 128;
    int rw = wid * 16;

    // ---- Q fragments: sum 4 fp32 partials, then split ----
    uint32_t qh[4], ql[4];
    {
        size_t row_a = (size_t)(b * NSEQ + r0 + rw + g);
        size_t row_b = row_a + 8;
        int col0 = h * HDIM + 2 * tq;
#pragma unroll
        for (int pos = 0; pos < 4; pos++) {
            size_t row = (pos & 1) ? row_b : row_a;
            int col = col0 + ((pos >> 1) ? 8 : 0);
            float sx = 0.f, sy = 0.f;
#pragma unroll
            for (int p = 0; p < 4; p++) {
                float2 v = *reinterpret_cast<const float2*>(
                    gQpart + (size_t)p * NROWS * EMB + row * EMB + col);
                sx += v.x; sy += v.y;
            }
            split2h(sx, sy, qh[pos], ql[pos]);
        }
    }

    float o1[2][4] = {{0,0,0,0},{0,0,0,0}};
    float o2[2][4] = {{0,0,0,0},{0,0,0,0}};
    float la1 = 0.f, lb1 = 0.f, la2 = 0.f, lb2 = 0.f;

    int sidx = t & 127;
    int sm = sidx >> 2, pp = (sidx & 3) * 2;   // key row, u32 pair index {0,2,4,6}
    bool first_half = (t < 128);
    const uint32_t* srcKh = first_half ? gKh : gKeh;
    const uint32_t* srcVh = first_half ? gVh : gVeh;
    int cbase = first_half ? 0 : 1;

    const float* maskrow0 = mask + ((size_t)(b * NSEQ + r0 + rw + g) * NSEQ);
    const float* maskrow1 = maskrow0 + 8 * NSEQ;

    // per-lane ldmatrix offsets (bytes)
    int l15 = lane & 15;
    int offK = (l15 & 7) * 48 + ((l15 >> 3) << 4);
    int offV = l15 * 48;

    // prefetch chunk 0
    KVr pf;
    {
        size_t off = (size_t)(b * NSEQ + sm) * PR + h * 8 + pp;
        pf.kh = *reinterpret_cast<const uint2*>(srcKh + off);
        pf.vh = *reinterpret_cast<const uint2*>(srcVh + off);
    }

    int buf = 0;
    for (int ch = 0; ch < 16; ch++) {
        {
            int di = sm * KStr + pp;
            *reinterpret_cast<uint2*>(&sK[buf][cbase][di]) = pf.kh;
            *reinterpret_cast<uint2*>(&sV[buf][cbase][di]) = pf.vh;
        }
        __syncthreads();
        if (ch < 15) {
            size_t off = (size_t)(b * NSEQ + (ch + 1) * 32 + sm) * PR + h * 8 + pp;
            pf.kh = *reinterpret_cast<const uint2*>(srcKh + off);
            pf.vh = *reinterpret_cast<const uint2*>(srcVh + off);
        }
        int c0 = ch * 32;

        uint32_t aK1 = smem_u32(&sK[buf][0][0]) + offK;
        uint32_t aK2 = smem_u32(&sK[buf][1][0]) + offK;
        uint32_t aV1 = smem_u32(&sV[buf][0][0]) + offV;
        uint32_t aV2 = smem_u32(&sV[buf][1][0]) + offV;

        float S1[4][4], S2[4][4];
#pragma unroll
        for (int nt = 0; nt < 4; nt++) {
#pragma unroll
            for (int j = 0; j < 4; j++) { S1[nt][j] = 0.f; S2[nt][j] = 0.f; }
            uint32_t b0, b1;
            LDSM_X2(b0, b1, aK1 + nt * 384);
            mma_f16(S1[nt], qh[0], qh[1], qh[2], qh[3], b0, b1);
            mma_f16(S1[nt], ql[0], ql[1], ql[2], ql[3], b0, b1);
            uint32_t e0, e1;
            LDSM_X2(e0, e1, aK2 + nt * 384);
            mma_f16(S2[nt], qh[0], qh[1], qh[2], qh[3], e0, e1);
            mma_f16(S2[nt], ql[0], ql[1], ql[2], ql[3], e0, e1);
        }

#pragma unroll
        for (int nt = 0; nt < 4; nt++) {
            int cc = c0 + nt * 8 + tq * 2;
            float2 m0 = *reinterpret_cast<const float2*>(maskrow0 + cc);
            float2 m1 = *reinterpret_cast<const float2*>(maskrow1 + cc);
            float p;
            p = __expf(fminf(fmaf(S1[nt][0], 0.25f, m0.x), 10.f)); S1[nt][0] = p; la1 += p;
            p = __expf(fminf(fmaf(S1[nt][1], 0.25f, m0.y), 10.f)); S1[nt][1] = p; la1 += p;
            p = __expf(fminf(fmaf(S1[nt][2], 0.25f, m1.x), 10.f)); S1[nt][2] = p; lb1 += p;
            p = __expf(fminf(fmaf(S1[nt][3], 0.25f, m1.y), 10.f)); S1[nt][3] = p; lb1 += p;
            p = __expf(fminf(fmaf(S2[nt][0], 0.25f, m0.x), 10.f)); S2[nt][0] = p; la2 += p;
            p = __expf(fminf(fmaf(S2[nt][1], 0.25f, m0.y), 10.f)); S2[nt][1] = p; la2 += p;
            p = __expf(fminf(fmaf(S2[nt][2], 0.25f, m1.x), 10.f)); S2[nt][2] = p; lb2 += p;
            p = __expf(fminf(fmaf(S2[nt][3], 0.25f, m1.y), 10.f)); S2[nt][3] = p; lb2 += p;
        }

#pragma unroll
        for (int ks = 0; ks < 2; ks++) {
            uint32_t a1h[4], a1l[4], a2h[4], a2l[4];
            split2h(S1[2*ks][0],   S1[2*ks][1],   a1h[0], a1l[0]);
            split2h(S1[2*ks][2],   S1[2*ks][3],   a1h[1], a1l[1]);
            split2h(S1[2*ks+1][0], S1[2*ks+1][1], a1h[2], a1l[2]);
            split2h(S1[2*ks+1][2], S1[2*ks+1][3], a1h[3], a1l[3]);
            split2h(S2[2*ks][0],   S2[2*ks][1],   a2h[0], a2l[0]);
            split2h(S2[2*ks][2],   S2[2*ks][3],   a2h[1], a2l[1]);
            split2h(S2[2*ks+1][0], S2[2*ks+1][1], a2h[2], a2l[2]);
            split2h(S2[2*ks+1][2], S2[2*ks+1][3], a2h[3], a2l[3]);
            uint32_t kof = (uint32_t)(ks * 16) * 48;
#pragma unroll
            for (int dt = 0; dt < 2; dt++) {
                uint32_t dof = kof + dt * 16;
                uint32_t v0, v1;
                LDSM_X2_T(v0, v1, aV1 + dof);
                mma_f16(o1[dt], a1h[0], a1h[1], a1h[2], a1h[3], v0, v1);
                mma_f16(o1[dt], a1l[0], a1l[1], a1l[2], a1l[3], v0, v1);
                uint32_t w0, w1;
                LDSM_X2_T(w0, w1, aV2 + dof);
                mma_f16(o2[dt], a2h[0], a2h[1], a2h[2], a2h[3], w0, w1);
                mma_f16(o2[dt], a2l[0], a2l[1], a2l[2], a2l[3], w0, w1);
            }
        }
        buf ^= 1;
    }

    la1 += __shfl_xor_sync(0xffffffffu, la1, 1); la1 += __shfl_xor_sync(0xffffffffu, la1, 2);
    lb1 += __shfl_xor_sync(0xffffffffu, lb1, 1); lb1 += __shfl_xor_sync(0xffffffffu, lb1, 2);
    la2 += __shfl_xor_sync(0xffffffffu, la2, 1); la2 += __shfl_xor_sync(0xffffffffu, la2, 2);
    lb2 += __shfl_xor_sync(0xffffffffu, lb2, 1); lb2 += __shfl_xor_sync(0xffffffffu, lb2, 2);
    float ia1 = 1.f / la1, ib1 = 1.f / lb1, ia2 = 1.f / la2, ib2 = 1.f / lb2;

    {
        size_t ra = (size_t)(b * NSEQ + r0 + rw + g) * PR + h * 8;
        size_t rb = ra + 8 * PR;
#pragma unroll
        for (int dt = 0; dt < 2; dt++) {
            int pair = dt * 4 + tq;
            uint32_t hh, ll;
            split2h(o1[dt][0] * ia1, o1[dt][1] * ia1, hh, ll);
            gO1h[ra + pair] = hh; gO1l[ra + pair] = ll;
            split2h(o1[dt][2] * ib1, o1[dt][3] * ib1, hh, ll);
            gO1h[rb + pair] = hh; gO1l[rb + pair] = ll;
            split2h(o2[dt][0] * ia2, o2[dt][1] * ia2, hh, ll);
            gO2h[ra + pair] = hh; gO2l[ra + pair] = ll;
            split2h(o2[dt][2] * ib2, o2[dt][3] * ib2, hh, ll);
            gO2h[rb + pair] = hh; gO2l[rb + pair] = ll;
        }
    }
}

// ---------------- in-place row softmax (no max pass: logits bounded) ----
__global__ void softmax_kernel(float* __restrict__ out) {
    float4* p = reinterpret_cast<float4*>(out + (size_t)blockIdx.x * NSEQ);
    int t = threadIdx.x;  // 128 threads
    float4 v = p[t];
    v.x = __expf(v.x); v.y = __expf(v.y);
    v.z = __expf(v.z); v.w = __expf(v.w);
    float sum = v.x + v.y + v.z + v.w;
#pragma unroll
    for (int o = 16; o; o >>= 1) sum += __shfl_xor_sync(0xffffffffu, sum, o);
    __shared__ float ss[4];
    if ((t & 31) == 0) ss[t >> 5] = sum;
    __syncthreads();
    sum = ss[0] + ss[1] + ss[2] + ss[3];

    float inv = 1.f / sum;
    v.x *= inv; v.y *= inv; v.z *= inv; v.w *= inv;
    p[t] = v;
}

// ---------------- launch ----------------
extern "C" void kernel_launch(void* const* d_in, const int* in_sizes, int n_in,
                              void* d_out, int out_size) {
    const float* enc_nodes = (const float*)d_in[0];
    const float* enc_graph = (const float*)d_in[1];
    const float* enc_q1    = (const float*)d_in[2];
    const float* enc_fg    = (const float*)d_in[3];
    const float* enc_ln    = (const float*)d_in[4];
    const float* enc_lg    = (const float*)d_in[5];
    const float* mask      = (const float*)d_in[6];
    const float* Wq_first  = (const float*)d_in[7];
    const float* Wq_last   = (const float*)d_in[8];
    const float* Wk        = (const float*)d_in[9];
    const float* Wv        = (const float*)d_in[10];
    const float* Wq_first_e= (const float*)d_in[11];
    const float* Wq_last_e = (const float*)d_in[12];
    const float* Wk_e      = (const float*)d_in[13];
    const float* Wv_e      = (const float*)d_in[14];
    const float* Wcomb1    = (const float*)d_in[15];
    const float* bcomb1    = (const float*)d_in[16];
    const float* Wcomb2    = (const float*)d_in[17];
    const float* bcomb2    = (const float*)d_in[18];
    float* out = (float*)d_out;

    prep_w<<<dim3(32, 10), 256>>>(Wk, Wv, Wk_e, Wv_e,
                                  Wq_first, Wq_last, Wq_first_e, Wq_last_e,
                                  Wcomb1, Wcomb2);
    prep_in<<<(NROWS * PR) / 256, 256>>>(enc_nodes, enc_graph);
    gemm_all<<<dim3(256, 8), 256>>>(enc_q1, enc_ln, enc_fg, enc_lg);
    attn_kernel<<<dim3(NHEAD, 4, BATCH), 256>>>(mask);
    comb_k<<<256, 256>>>(bcomb1, bcomb2);
    score_k<<<dim3(4, 8, BATCH), 256>>>(mask, out);
    softmax_kernel<<<BATCH * NSEQ, 128>>>(out);
}

// round 17
// speedup vs baseline: 1.0691x; 1.0303x over previous
#include <cuda_runtime.h>
#include <cuda_fp16.h>
#include <math.h>
#include <stdint.h>

#define BATCH 32
#define NSEQ  512
#define EMB   128
#define NHEAD 8
#define HDIM  16
#define NROWS (BATCH*NSEQ)

// ---------------- scratch (u32 = half2; [row][64 pairs]) ----------------
#define PR 64
// A-side operands: split (hi + lo)
__device__ __align__(16) uint32_t gNh[NROWS*PR],  gNl[NROWS*PR];
__device__ __align__(16) uint32_t gGh[NROWS*PR],  gGl[NROWS*PR];
__device__ __align__(16) uint32_t gO1h[NROWS*PR], gO1l[NROWS*PR];
__device__ __align__(16) uint32_t gO2h[NROWS*PR], gO2l[NROWS*PR];
__device__ __align__(16) uint32_t gMHh[NROWS*PR], gMHl[NROWS*PR];
// B-side operands: hi only
__device__ __align__(16) uint32_t gSHKh[NROWS*PR];
__device__ __align__(16) uint32_t gKh[NROWS*PR],  gVh[NROWS*PR];
__device__ __align__(16) uint32_t gKeh[NROWS*PR], gVeh[NROWS*PR];
__device__ __align__(16) uint32_t gWh[10*8192];
// fp32 K-split partials for qproj
__device__ __align__(16) float gQpart[4*NROWS*EMB];

__device__ __forceinline__ float fast_tanh(float x) {
    float e = __expf(2.f * x);
    return 1.f - __fdividef(2.f, e + 1.f);
}

__device__ __forceinline__ uint32_t cvt2h(float x, float y) {
    __half2 hv = __floats2half2_rn(x, y);
    return *reinterpret_cast<uint32_t*>(&hv);
}
__device__ __forceinline__ void split2h(float x, float y, uint32_t& h, uint32_t& l) {
    __half2 hv = __floats2half2_rn(x, y);
    h = *reinterpret_cast<uint32_t*>(&hv);
    float2 hf = __half22float2(hv);
    __half2 lv = __floats2half2_rn(x - hf.x, y - hf.y);
    l = *reinterpret_cast<uint32_t*>(&lv);
}

__device__ __forceinline__ void mma_f16(float* d,
        uint32_t a0, uint32_t a1, uint32_t a2, uint32_t a3,
        uint32_t b0, uint32_t b1) {
    asm volatile(
        "mma.sync.aligned.m16n8k16.row.col.f32.f16.f16.f32 "
        "{%0,%1,%2,%3}, {%4,%5,%6,%7}, {%8,%9}, {%0,%1,%2,%3};"
        : "+f"(d[0]), "+f"(d[1]), "+f"(d[2]), "+f"(d[3])
        : "r"(a0), "r"(a1), "r"(a2), "r"(a3), "r"(b0), "r"(b1));
}

__device__ __forceinline__ uint32_t smem_u32(const void* p) {
    uint32_t a;
    asm("{ .reg .u64 t; cvta.to.shared.u64 t, %1; cvt.u32.u64 %0, t; }"
        : "=r"(a) : "l"(p));
    return a;
}
#define LDSM_X2(r0, r1, addr) \
    asm volatile("ldmatrix.sync.aligned.m8n8.x2.shared.b16 {%0,%1}, [%2];" \
                 : "=r"(r0), "=r"(r1) : "r"(addr))
#define LDSM_X2_T(r0, r1, addr) \
    asm volatile("ldmatrix.sync.aligned.m8n8.x2.trans.shared.b16 {%0,%1}, [%2];" \
                 : "=r"(r0), "=r"(r1) : "r"(addr))

// ======================================================================
// prep: merged inputs + weights. grid (4096 + 320), block 256.
//   bid < 4096: inputs (nodes/graph/shk rows)
//   bid >= 4096: weights (10 matrices, 32 blocks each)
// ======================================================================
__global__ void __launch_bounds__(256) prep_all(
        const float* __restrict__ nodes, const float* __restrict__ graph,
        const float* __restrict__ W0, const float* __restrict__ W1,
        const float* __restrict__ W2, const float* __restrict__ W3,
        const float* __restrict__ W4, const float* __restrict__ W5,
        const float* __restrict__ W6, const float* __restrict__ W7,
        const float* __restrict__ W8, const float* __restrict__ W9) {
    int bid = blockIdx.x;
    if (bid < 4096) {
        int i = bid * 256 + threadIdx.x;
        int row = i >> 6, kp = i & 63;
        float2 n2 = *reinterpret_cast<const float2*>(&nodes[(size_t)row * 128 + 2 * kp]);
        float2 g2 = *reinterpret_cast<const float2*>(&graph[(size_t)row * 128 + 2 * kp]);
        uint32_t h, l;
        split2h(n2.x, n2.y, h, l);  gNh[i] = h;  gNl[i] = l;
        split2h(g2.x, g2.y, h, l);  gGh[i] = h;  gGl[i] = l;
        gSHKh[i] = cvt2h(n2.x + g2.x, n2.y + g2.y);
    } else {
        const float* Ws[10] = {W0, W1, W2, W3, W4, W5, W6, W7, W8, W9};
        int wb = bid - 4096;
        int w = wb >> 5;
        int i = (wb & 31) * 256 + threadIdx.x;   // 0..8191
        int n = i >> 6, kp = i & 63;
        const float* W = Ws[w];
        gWh[w * 8192 + i] = cvt2h(W[(2 * kp) * 128 + n], W[(2 * kp + 1) * 128 + n]);
    }
}

// ======================================================================
// GEMM machinery: M-tile 64, N 128, BK 16 (8 pairs), double-buffered.
// A split (h+l), B hi-only. 2 MMAs per (nt, k-step).
// ======================================================================
#define SStr 12

struct U2x2 { uint2 h, l; };

__device__ __forceinline__ U2x2 ldAcp(const uint32_t* __restrict__ srcH,
                                      const uint32_t* __restrict__ srcL,
                                      int row0, int kp0, int t) {
    int r = t >> 2, pp = (t & 3) * 2;
    size_t off = (size_t)(row0 + r) * PR + kp0 + pp;
    U2x2 v;
    v.h = *reinterpret_cast<const uint2*>(srcH + off);
    v.l = *reinterpret_cast<const uint2*>(srcL + off);
    return v;
}
__device__ __forceinline__ void stAcp(U2x2 v, int t, uint32_t* sAh, uint32_t* sAl) {
    int r = t >> 2, pp = (t & 3) * 2;
    sAh[r * SStr + pp] = v.h.x; sAh[r * SStr + pp + 1] = v.h.y;
    sAl[r * SStr + pp] = v.l.x; sAl[r * SStr + pp + 1] = v.l.y;
}

__device__ __forceinline__ uint4 ldBcp(const uint32_t* __restrict__ srcH,
                                       int kp0, int t) {
    int n = t >> 1, kq = (t & 1) * 4;
    return *reinterpret_cast<const uint4*>(srcH + (size_t)n * PR + kp0 + kq);
}
__device__ __forceinline__ void stBcp(uint4 v, int t, uint32_t* sBh) {
    int n = t >> 1, kq = (t & 1) * 4;
    sBh[n * SStr + kq]     = v.x; sBh[n * SStr + kq + 1] = v.y;
    sBh[n * SStr + kq + 2] = v.z; sBh[n * SStr + kq + 3] = v.w;
}

__device__ __forceinline__ float4 ldA64(const float* __restrict__ X, int row0, int k0, int t) {
    int r = t >> 2, k4 = (t & 3) * 4;
    return *reinterpret_cast<const float4*>(&X[(size_t)(row0 + r) * 128 + k0 + k4]);
}
__device__ __forceinline__ void stA64(float4 v, int t, uint32_t* sh, uint32_t* sl) {
    int r = t >> 2, k4 = (t & 3) * 4;
    uint32_t h0, l0, h1, l1;
    split2h(v.x, v.y, h0, l0);
    split2h(v.z, v.w, h1, l1);
    int base = r * SStr + (k4 >> 1);
    sh[base] = h0; sh[base + 1] = h1;
    sl[base] = l0; sl[base + 1] = l1;
}

__device__ __forceinline__ void mma64(const uint32_t* __restrict__ sAh,
                                      const uint32_t* __restrict__ sAl,
                                      const uint32_t* __restrict__ sBh,
                                      int mg, int nh, int g, int tq, float acc[8][4]) {
    int m0 = mg * 16;
    uint32_t ah0 = sAh[(m0 + g) * SStr + tq],     ah1 = sAh[(m0 + 8 + g) * SStr + tq];
    uint32_t ah2 = sAh[(m0 + g) * SStr + tq + 4], ah3 = sAh[(m0 + 8 + g) * SStr + tq + 4];
    uint32_t al0 = sAl[(m0 + g) * SStr + tq],     al1 = sAl[(m0 + 8 + g) * SStr + tq];
    uint32_t al2 = sAl[(m0 + g) * SStr + tq + 4], al3 = sAl[(m0 + 8 + g) * SStr + tq + 4];
#pragma unroll
    for (int nt = 0; nt < 8; nt++) {
        int n = nh * 64 + nt * 8 + g;
        uint32_t bh0 = sBh[n * SStr + tq], bh1 = sBh[n * SStr + tq + 4];
        mma_f16(acc[nt], ah0, ah1, ah2, ah3, bh0, bh1);
        mma_f16(acc[nt], al0, al1, al2, al3, bh0, bh1);
    }
}

// epilogue writing hi-only (for K/V)
__device__ __forceinline__ void epi_h(float acc[8][4], int row0, int mg, int nh,
                                      int g, int tq, uint32_t* __restrict__ dh) {
    size_t r_lo = (size_t)row0 + mg * 16 + g;
    size_t r_hi = r_lo + 8;
#pragma unroll
    for (int nt = 0; nt < 8; nt++) {
        int pair = nh * 32 + nt * 4 + tq;
        dh[r_lo * PR + pair] = cvt2h(acc[nt][0], acc[nt][1]);
        dh[r_hi * PR + pair] = cvt2h(acc[nt][2], acc[nt][3]);
    }
}
// epilogue writing split (for O/MH)
__device__ __forceinline__ void epi_split(float acc[8][4], int row0, int mg, int nh,
                                          int g, int tq,
                                          uint32_t* __restrict__ dh, uint32_t* __restrict__ dl) {
    size_t r_lo = (size_t)row0 + mg * 16 + g;
    size_t r_hi = r_lo + 8;
#pragma unroll
    for (int nt = 0; nt < 8; nt++) {
        int pair = nh * 32 + nt * 4 + tq;
        uint32_t h, l;
        split2h(acc[nt][0], acc[nt][1], h, l);
        dh[r_lo * PR + pair] = h; dl[r_lo * PR + pair] = l;
        split2h(acc[nt][2], acc[nt][3], h, l);
        dh[r_hi * PR + pair] = h; dl[r_hi * PR + pair] = l;
    }
}

__device__ __forceinline__ void epi_f32(float acc[8][4], int row0, int mg, int nh,
                                        int g, int tq, float* __restrict__ dst) {
    size_t r_lo = (size_t)row0 + mg * 16 + g;
    size_t r_hi = r_lo + 8;
#pragma unroll
    for (int nt = 0; nt < 8; nt++) {
        int c = nh * 64 + nt * 8 + tq * 2;
        *reinterpret_cast<float2*>(dst + r_lo * EMB + c) = make_float2(acc[nt][0], acc[nt][1]);
        *reinterpret_cast<float2*>(dst + r_hi * EMB + c) = make_float2(acc[nt][2], acc[nt][3]);
    }
}

// ======================================================================
// gemm_all: grid (256, 8), block 256.
// ======================================================================
__global__ void __launch_bounds__(256) gemm_all(
        const float* __restrict__ X0, const float* __restrict__ X1,
        const float* __restrict__ X2, const float* __restrict__ X3) {
    __shared__ uint32_t sAh[2][64 * SStr], sAl[2][64 * SStr];
    __shared__ uint32_t sBh[2][128 * SStr];
    int z = blockIdx.y;
    int t = threadIdx.x;
    int lane = t & 31, wid = t >> 5;
    int g = lane >> 2, tq = lane & 3;
    int mg = wid >> 1, nh = wid & 1;
    int row0 = blockIdx.x * 64;

    const uint32_t* Bh = gWh + (size_t)z * 8192;

    float acc[8][4];
#pragma unroll
    for (int nt = 0; nt < 8; nt++)
#pragma unroll
        for (int j = 0; j < 4; j++) acc[nt][j] = 0.f;

    if (z < 4) {
        const uint32_t* Ah = (z < 2) ? gNh : gGh;
        const uint32_t* Al = (z < 2) ? gNl : gGl;
        U2x2 pa = ldAcp(Ah, Al, row0, 0, t);
        uint4 pb = ldBcp(Bh, 0, t);
        int buf = 0;
        for (int s = 0; s < 8; s++) {
            stAcp(pa, t, sAh[buf], sAl[buf]);
            stBcp(pb, t, sBh[buf]);
            __syncthreads();
            if (s < 7) {
                pa = ldAcp(Ah, Al, row0, (s + 1) * 8, t);
                pb = ldBcp(Bh, (s + 1) * 8, t);
            }
            mma64(sAh[buf], sAl[buf], sBh[buf], mg, nh, g, tq, acc);
            buf ^= 1;
        }
        uint32_t* Oh = (z == 0) ? gKh : (z == 1) ? gVh : (z == 2) ? gKeh : gVeh;
        epi_h(acc, row0, mg, nh, g, tq, Oh);
    } else {
        const float* Xs[4] = {X0, X1, X2, X3};
        const float* X = Xs[z - 4];
        float4 pa = ldA64(X, row0, 0, t);
        uint4 pb = ldBcp(Bh, 0, t);
        int buf = 0;
        for (int s = 0; s < 8; s++) {
            stA64(pa, t, sAh[buf], sAl[buf]);
            stBcp(pb, t, sBh[buf]);
            __syncthreads();
            if (s < 7) {
                pa = ldA64(X, row0, (s + 1) * 16, t);
                pb = ldBcp(Bh, (s + 1) * 8, t);
            }
            mma64(sAh[buf], sAl[buf], sBh[buf], mg, nh, g, tq, acc);
            buf ^= 1;
        }
        epi_f32(acc, row0, mg, nh, g, tq, gQpart + (size_t)(z - 4) * NROWS * EMB);
    }
}

// ======================================================================
// comb_k: MH = O1@W8 + O2@W9 + biases. grid (256), block 256. 16 steps.
// ======================================================================
__global__ void __launch_bounds__(256) comb_k(
        const float* __restrict__ b1, const float* __restrict__ b2) {
    __shared__ uint32_t sAh[2][64 * SStr], sAl[2][64 * SStr];
    __shared__ uint32_t sBh[2][128 * SStr];
    int t = threadIdx.x;
    int lane = t & 31, wid = t >> 5;
    int g = lane >> 2, tq = lane & 3;
    int mg = wid >> 1, nh = wid & 1;
    int row0 = blockIdx.x * 64;

    float acc[8][4];
#pragma unroll
    for (int nt = 0; nt < 8; nt++)
#pragma unroll
        for (int j = 0; j < 4; j++) acc[nt][j] = 0.f;

    U2x2 pa = ldAcp(gO1h, gO1l, row0, 0, t);
    uint4 pb = ldBcp(gWh + 8 * 8192, 0, t);
    int buf = 0;
    for (int s = 0; s < 16; s++) {
        stAcp(pa, t, sAh[buf], sAl[buf]);
        stBcp(pb, t, sBh[buf]);
        __syncthreads();
        if (s < 15) {
            int p = (s + 1) >> 3, kp0 = ((s + 1) & 7) * 8;
            const uint32_t* ah = p ? gO2h : gO1h;
            const uint32_t* al = p ? gO2l : gO1l;
            pa = ldAcp(ah, al, row0, kp0, t);
            pb = ldBcp(gWh + (size_t)(8 + p) * 8192, kp0, t);
        }
        mma64(sAh[buf], sAl[buf], sBh[buf], mg, nh, g, tq, acc);
        buf ^= 1;
    }

#pragma unroll
    for (int nt = 0; nt < 8; nt++) {
        int c = nh * 64 + nt * 8 + tq * 2;
        float2 bb1 = *reinterpret_cast<const float2*>(&b1[c]);
        float2 bb2 = *reinterpret_cast<const float2*>(&b2[c]);
        acc[nt][0] += bb1.x + bb2.x; acc[nt][1] += bb1.y + bb2.y;
        acc[nt][2] += bb1.x + bb2.x; acc[nt][3] += bb1.y + bb2.y;
    }
    epi_split(acc, row0, mg, nh, g, tq, gMHh, gMHl);
}

// ======================================================================
// score: logits = 10*tanh((MH @ shk^T)/sqrt(128)) + mask
// grid (4, 8, BATCH), block 256.
// ======================================================================
__global__ void __launch_bounds__(256) score_k(
        const float* __restrict__ mask, float* __restrict__ out) {
    __shared__ uint32_t sAh[2][64 * SStr], sAl[2][64 * SStr];
    __shared__ uint32_t sBh[2][128 * SStr];
    int t = threadIdx.x;
    int lane = t & 31, wid = t >> 5;
    int g = lane >> 2, tq = lane & 3;
    int mg = wid >> 1, nh = wid & 1;
    int b = blockIdx.z;
    int c0 = blockIdx.x * 128, r0 = blockIdx.y * 64;
    int arow0 = b * NSEQ + r0;
    const uint32_t* Bh = gSHKh + (size_t)(b * NSEQ + c0) * PR;

    float acc[8][4];
#pragma unroll
    for (int nt = 0; nt < 8; nt++)
#pragma unroll
        for (int j = 0; j < 4; j++) acc[nt][j] = 0.f;

    U2x2 pa = ldAcp(gMHh, gMHl, arow0, 0, t);
    uint4 pb = ldBcp(Bh, 0, t);
    int buf = 0;
    for (int s = 0; s < 8; s++) {
        stAcp(pa, t, sAh[buf], sAl[buf]);
        stBcp(pb, t, sBh[buf]);
        __syncthreads();
        if (s < 7) {
            pa = ldAcp(gMHh, gMHl, arow0, (s + 1) * 8, t);
            pb = ldBcp(Bh, (s + 1) * 8, t);
        }
        mma64(sAh[buf], sAl[buf], sBh[buf], mg, nh, g, tq, acc);
        buf ^= 1;
    }

    const float inv_sqrt_emb = 0.08838834764831845f;  // 1/sqrt(128)
    int r_lo = r0 + mg * 16 + g;
    int r_hi = r_lo + 8;
#pragma unroll
    for (int nt = 0; nt < 8; nt++) {
        int c = c0 + nh * 64 + nt * 8 + tq * 2;
        size_t gi0 = (size_t)(b * NSEQ + r_lo) * NSEQ + c;
        size_t gi1 = (size_t)(b * NSEQ + r_hi) * NSEQ + c;
        float2 m0 = *reinterpret_cast<const float2*>(&mask[gi0]);
        float2 m1 = *reinterpret_cast<const float2*>(&mask[gi1]);
        *reinterpret_cast<float2*>(&out[gi0]) = make_float2(
            fmaf(10.f, fast_tanh(acc[nt][0] * inv_sqrt_emb), m0.x),
            fmaf(10.f, fast_tanh(acc[nt][1] * inv_sqrt_emb), m0.y));
        *reinterpret_cast<float2*>(&out[gi1]) = make_float2(
            fmaf(10.f, fast_tanh(acc[nt][2] * inv_sqrt_emb), m1.x),
            fmaf(10.f, fast_tanh(acc[nt][3] * inv_sqrt_emb), m1.y));
    }
}

// ======================================================================
// dual attention: fp16 2-term, r13 structure, NO clamp (never binds).
// Double-buffered + prefetch, one sync/chunk. grid (NHEAD, 4, BATCH).
// ======================================================================
#define KStr 12   // u32 stride per key row (48B)
struct KVr { uint2 kh, vh; };

__global__ void __launch_bounds__(256) attn_kernel(const float* __restrict__ mask) {
    // [buf][attn]: 0 = attn1, 1 = attn2
    __shared__ __align__(16) uint32_t sK[2][2][32 * KStr];
    __shared__ __align__(16) uint32_t sV[2][2][32 * KStr];

    int t = threadIdx.x;
    int lane = t & 31, wid = t >> 5;
    int g = lane >> 2, tq = lane & 3;
    int b = blockIdx.z, h = blockIdx.x;
    int r0 = blockIdx.y * 128;
    int rw = wid * 16;

    // ---- Q fragments: sum 4 fp32 partials, then split ----
    uint32_t qh[4], ql[4];
    {
        size_t row_a = (size_t)(b * NSEQ + r0 + rw + g);
        size_t row_b = row_a + 8;
        int col0 = h * HDIM + 2 * tq;
#pragma unroll
        for (int pos = 0; pos < 4; pos++) {
            size_t row = (pos & 1) ? row_b : row_a;
            int col = col0 + ((pos >> 1) ? 8 : 0);
            float sx = 0.f, sy = 0.f;
#pragma unroll
            for (int p = 0; p < 4; p++) {
                float2 v = *reinterpret_cast<const float2*>(
                    gQpart + (size_t)p * NROWS * EMB + row * EMB + col);
                sx += v.x; sy += v.y;
            }
            split2h(sx, sy, qh[pos], ql[pos]);
        }
    }

    float o1[2][4] = {{0,0,0,0},{0,0,0,0}};
    float o2[2][4] = {{0,0,0,0},{0,0,0,0}};
    float la1 = 0.f, lb1 = 0.f, la2 = 0.f, lb2 = 0.f;

    int sidx = t & 127;
    int sm = sidx >> 2, pp = (sidx & 3) * 2;   // key row, u32 pair index {0,2,4,6}
    bool first_half = (t < 128);
    const uint32_t* srcKh = first_half ? gKh : gKeh;
    const uint32_t* srcVh = first_half ? gVh : gVeh;
    int cbase = first_half ? 0 : 1;

    const float* maskrow0 = mask + ((size_t)(b * NSEQ + r0 + rw + g) * NSEQ);
    const float* maskrow1 = maskrow0 + 8 * NSEQ;

    // per-lane ldmatrix offsets (bytes)
    int l15 = lane & 15;
    int offK = (l15 & 7) * 48 + ((l15 >> 3) << 4);
    int offV = l15 * 48;

    // prefetch chunk 0
    KVr pf;
    {
        size_t off = (size_t)(b * NSEQ + sm) * PR + h * 8 + pp;
        pf.kh = *reinterpret_cast<const uint2*>(srcKh + off);
        pf.vh = *reinterpret_cast<const uint2*>(srcVh + off);
    }

    int buf = 0;
    for (int ch = 0; ch < 16; ch++) {
        {
            int di = sm * KStr + pp;
            *reinterpret_cast<uint2*>(&sK[buf][cbase][di]) = pf.kh;
            *reinterpret_cast<uint2*>(&sV[buf][cbase][di]) = pf.vh;
        }
        __syncthreads();
        if (ch < 15) {
            size_t off = (size_t)(b * NSEQ + (ch + 1) * 32 + sm) * PR + h * 8 + pp;
            pf.kh = *reinterpret_cast<const uint2*>(srcKh + off);
            pf.vh = *reinterpret_cast<const uint2*>(srcVh + off);
        }
        int c0 = ch * 32;

        uint32_t aK1 = smem_u32(&sK[buf][0][0]) + offK;
        uint32_t aK2 = smem_u32(&sK[buf][1][0]) + offK;
        uint32_t aV1 = smem_u32(&sV[buf][0][0]) + offV;
        uint32_t aV2 = smem_u32(&sV[buf][1][0]) + offV;

        float S1[4][4], S2[4][4];
#pragma unroll
        for (int nt = 0; nt < 4; nt++) {
#pragma unroll
            for (int j = 0; j < 4; j++) { S1[nt][j] = 0.f; S2[nt][j] = 0.f; }
            uint32_t b0, b1;
            LDSM_X2(b0, b1, aK1 + nt * 384);
            mma_f16(S1[nt], qh[0], qh[1], qh[2], qh[3], b0, b1);
            mma_f16(S1[nt], ql[0], ql[1], ql[2], ql[3], b0, b1);
            uint32_t e0, e1;
            LDSM_X2(e0, e1, aK2 + nt * 384);
            mma_f16(S2[nt], qh[0], qh[1], qh[2], qh[3], e0, e1);
            mma_f16(S2[nt], ql[0], ql[1], ql[2], ql[3], e0, e1);
        }

#pragma unroll
        for (int nt = 0; nt < 4; nt++) {
            int cc = c0 + nt * 8 + tq * 2;
            float2 m0 = *reinterpret_cast<const float2*>(maskrow0 + cc);
            float2 m1 = *reinterpret_cast<const float2*>(maskrow1 + cc);
            float p;
            p = __expf(fmaf(S1[nt][0], 0.25f, m0.x)); S1[nt][0] = p; la1 += p;
            p = __expf(fmaf(S1[nt][1], 0.25f, m0.y)); S1[nt][1] = p; la1 += p;
            p = __expf(fmaf(S1[nt][2], 0.25f, m1.x)); S1[nt][2] = p; lb1 += p;
            p = __expf(fmaf(S1[nt][3], 0.25f, m1.y)); S1[nt][3] = p; lb1 += p;
            p = __expf(fmaf(S2[nt][0], 0.25f, m0.x)); S2[nt][0] = p; la2 += p;
            p = __expf(fmaf(S2[nt][1], 0.25f, m0.y)); S2[nt][1] = p; la2 += p;
            p = __expf(fmaf(S2[nt][2], 0.25f, m1.x)); S2[nt][2] = p; lb2 += p;
            p = __expf(fmaf(S2[nt][3], 0.25f, m1.y)); S2[nt][3] = p; lb2 += p;
        }

#pragma unroll
        for (int ks = 0; ks < 2; ks++) {
            uint32_t a1h[4], a1l[4], a2h[4], a2l[4];
            split2h(S1[2*ks][0],   S1[2*ks][1],   a1h[0], a1l[0]);
            split2h(S1[2*ks][2],   S1[2*ks][3],   a1h[1], a1l[1]);
            split2h(S1[2*ks+1][0], S1[2*ks+1][1], a1h[2], a1l[2]);
            split2h(S1[2*ks+1][2], S1[2*ks+1][3], a1h[3], a1l[3]);
            split2h(S2[2*ks][0],   S2[2*ks][1],   a2h[0], a2l[0]);
            split2h(S2[2*ks][2],   S2[2*ks][3],   a2h[1], a2l[1]);
            split2h(S2[2*ks+1][0], S2[2*ks+1][1], a2h[2], a2l[2]);
            split2h(S2[2*ks+1][2], S2[2*ks+1][3], a2h[3], a2l[3]);
            uint32_t kof = (uint32_t)(ks * 16) * 48;
#pragma unroll
            for (int dt = 0; dt < 2; dt++) {
                uint32_t dof = kof + dt * 16;
                uint32_t v0, v1;
                LDSM_X2_T(v0, v1, aV1 + dof);
                mma_f16(o1[dt], a1h[0], a1h[1], a1h[2], a1h[3], v0, v1);
                mma_f16(o1[dt], a1l[0], a1l[1], a1l[2], a1l[3], v0, v1);
                uint32_t w0, w1;
                LDSM_X2_T(w0, w1, aV2 + dof);
                mma_f16(o2[dt], a2h[0], a2h[1], a2h[2], a2h[3], w0, w1);
                mma_f16(o2[dt], a2l[0], a2l[1], a2l[2], a2l[3], w0, w1);
            }
        }
        buf ^= 1;
    }

    la1 += __shfl_xor_sync(0xffffffffu, la1, 1); la1 += __shfl_xor_sync(0xffffffffu, la1, 2);
    lb1 += __shfl_xor_sync(0xffffffffu, lb1, 1); lb1 += __shfl_xor_sync(0xffffffffu, lb1, 2);
    la2 += __shfl_xor_sync(0xffffffffu, la2, 1); la2 += __shfl_xor_sync(0xffffffffu, la2, 2);
    lb2 += __shfl_xor_sync(0xffffffffu, lb2, 1); lb2 += __shfl_xor_sync(0xffffffffu, lb2, 2);
    float ia1 = 1.f / la1, ib1 = 1.f / lb1, ia2 = 1.f / la2, ib2 = 1.f / lb2;

    {
        size_t ra = (size_t)(b * NSEQ + r0 + rw + g) * PR + h * 8;
        size_t rb = ra + 8 * PR;
#pragma unroll
        for (int dt = 0; dt < 2; dt++) {
            int pair = dt * 4 + tq;
            uint32_t hh, ll;
            split2h(o1[dt][0] * ia1, o1[dt][1] * ia1, hh, ll);
            gO1h[ra + pair] = hh; gO1l[ra + pair] = ll;
            split2h(o1[dt][2] * ib1, o1[dt][3] * ib1, hh, ll);
            gO1h[rb + pair] = hh; gO1l[rb + pair] = ll;
            split2h(o2[dt][0] * ia2, o2[dt][1] * ia2, hh, ll);
            gO2h[ra + pair] = hh; gO2l[ra + pair] = ll;
            split2h(o2[dt][2] * ib2, o2[dt][3] * ib2, hh, ll);
            gO2h[rb + pair] = hh; gO2l[rb + pair] = ll;
        }
    }
}

// ---------------- in-place row softmax (no max pass: logits bounded) ----
__global__ void softmax_kernel(float* __restrict__ out) {
    float4* p = reinterpret_cast<float4*>(out + (size_t)blockIdx.x * NSEQ);
    int t = threadIdx.x;  // 128 threads
    float4 v = p[t];
    v.x = __expf(v.x); v.y = __expf(v.y);
    v.z = __expf(v.z); v.w = __expf(v.w);
    float sum = v.x + v.y + v.z + v.w;
#pragma unroll
    for (int o = 16; o; o >>= 1) sum += __shfl_xor_sync(0xffffffffu, sum, o);
    __shared__ float ss[4];
    if ((t & 31) == 0) ss[t >> 5] = sum;
    __syncthreads();
    sum = ss[0] + ss[1] + ss[2] + ss[3];

    float inv = 1.f / sum;
    v.x *= inv; v.y *= inv; v.z *= inv; v.w *= inv;
    p[t] = v;
}

// ---------------- launch ----------------
extern "C" void kernel_launch(void* const* d_in, const int* in_sizes, int n_in,
                              void* d_out, int out_size) {
    const float* enc_nodes = (const float*)d_in[0];
    const float* enc_graph = (const float*)d_in[1];
    const float* enc_q1    = (const float*)d_in[2];
    const float* enc_fg    = (const float*)d_in[3];
    const float* enc_ln    = (const float*)d_in[4];
    const float* enc_lg    = (const float*)d_in[5];
    const float* mask      = (const float*)d_in[6];
    const float* Wq_first  = (const float*)d_in[7];
    const float* Wq_last   = (const float*)d_in[8];
    const float* Wk        = (const float*)d_in[9];
    const float* Wv        = (const float*)d_in[10];
    const float* Wq_first_e= (const float*)d_in[11];
    const float* Wq_last_e = (const float*)d_in[12];
    const float* Wk_e      = (const float*)d_in[13];
    const float* Wv_e      = (const float*)d_in[14];
    const float* Wcomb1    = (const float*)d_in[15];
    const float* bcomb1    = (const float*)d_in[16];
    const float* Wcomb2    = (const float*)d_in[17];
    const float* bcomb2    = (const float*)d_in[18];
    float* out = (float*)d_out;

    prep_all<<<4096 + 320, 256>>>(enc_nodes, enc_graph,
                                  Wk, Wv, Wk_e, Wv_e,
                                  Wq_first, Wq_last, Wq_first_e, Wq_last_e,
                                  Wcomb1, Wcomb2);
    gemm_all<<<dim3(256, 8), 256>>>(enc_q1, enc_ln, enc_fg, enc_lg);
    attn_kernel<<<dim3(NHEAD, 4, BATCH), 256>>>(mask);
    comb_k<<<256, 256>>>(bcomb1, bcomb2);
    score_k<<<dim3(4, 8, BATCH), 256>>>(mask, out);
    softmax_kernel<<<BATCH * NSEQ, 128>>>(out);
}